// round 16
// baseline (speedup 1.0000x reference)
#include <cuda_runtime.h>
#include <cuda_fp16.h>
#include <cuda_bf16.h>
#include <cstdint>
#include <cstddef>

// ---------------- problem constants ----------------
#define IN_F   1024
#define OUT_F  1024
#define MAX_TOKENS 32768
#define TILE_M 128
#define TILE_N 128

#define SM_STRIDE 2064    // prep-kernel smem row pad

// GEMM pipeline: chunk = 4 kb (2 kbp), 4-stage, 2 CTAs/SM, B as packed sign bits
#define KB_CH    4
#define NCHUNK   16                                  // 64 kb total
#define NSTAGE   4
#define A_CH_BYTES (8 * KB_CH * 32 * 16)             // 16384
#define B_CH_BYTES 1024                              // 16 ng x 2 kbp x 32 lanes x 1B
#define STAGE_BYTES (A_CH_BYTES + B_CH_BYTES)        // 17408
#define GEMM_SMEM (NSTAGE * STAGE_BYTES)             // 69632/CTA (x2 = 139KB/SM)

// ---------------- scratch ----------------
__device__ __align__(16) __nv_bfloat16 g_xa[(size_t)MAX_TOKENS * IN_F];
__device__ float g_xs[MAX_TOKENS];
// B sign bits: [n_blk 8][chunk 16][wn 4][lane 32][jj 4][kk 2] bytes, bit k = value k positive
__device__ __align__(16) uint8_t g_wbits[(size_t)OUT_F * IN_F / 8];
__device__ float g_ws[OUT_F];

// ---------------- helpers ----------------
static __device__ __forceinline__ void mma_bf16(float* c, uint32_t a0, uint32_t a1,
                                                uint32_t a2, uint32_t a3,
                                                uint32_t b0, uint32_t b1) {
    asm volatile(
        "mma.sync.aligned.m16n8k16.row.col.f32.bf16.bf16.f32 "
        "{%0,%1,%2,%3}, {%4,%5,%6,%7}, {%8,%9}, {%0,%1,%2,%3};"
        : "+f"(c[0]), "+f"(c[1]), "+f"(c[2]), "+f"(c[3])
        : "r"(a0), "r"(a1), "r"(a2), "r"(a3), "r"(b0), "r"(b1));
}
static __device__ __forceinline__ uint32_t bf16x2(float lo, float hi) {
    return (uint32_t)__bfloat16_as_ushort(__float2bfloat16_rn(lo))
         | ((uint32_t)__bfloat16_as_ushort(__float2bfloat16_rn(hi)) << 16);
}
static __device__ __forceinline__ uint32_t smem_u32(const void* p) {
    uint32_t a;
    asm("{ .reg .u64 t; cvta.to.shared.u64 t, %1; cvt.u32.u64 %0, t; }" : "=r"(a) : "l"(p));
    return a;
}
static __device__ __forceinline__ void cp16(uint32_t s, const void* g) {
    asm volatile("cp.async.cg.shared.global [%0], [%1], 16;" :: "r"(s), "l"(g));
}
static __device__ __forceinline__ void lds128(uint4& v, uint32_t addr) {
    asm volatile("ld.shared.v4.u32 {%0,%1,%2,%3}, [%4];"
                 : "=r"(v.x), "=r"(v.y), "=r"(v.z), "=r"(v.w) : "r"(addr));
}
static __device__ __forceinline__ void lds64(uint2& v, uint32_t addr) {
    asm volatile("ld.shared.v2.u32 {%0,%1}, [%2];"
                 : "=r"(v.x), "=r"(v.y) : "r"(addr));
}
// expand bits 2q,2q+1 of byte b -> bf16x2 of {+1,-1}
static __device__ __forceinline__ uint32_t bexp(uint32_t b, int q) {
    return 0xBF80BF80u ^ ((b << (15 - 2 * q)) & 0x8000u)
                       ^ ((b << (30 - 2 * q)) & 0x80000000u);
}

// ---------------- fused prep kernel ----------------
__global__ void __launch_bounds__(512) prep_kernel(const float* __restrict__ x,
                                                   const float* __restrict__ w,
                                                   int qBlocks) {
    __shared__ int8_t sm[16 * SM_STRIDE];
    int tid = threadIdx.x, warp = tid >> 5, lane = tid & 31;

    if ((int)blockIdx.x < qBlocks) {
        // ---- activation quantization (unchanged, proven) ----
        int mg = blockIdx.x;
        int t = mg * 16 + warp;
        const float4* xr = (const float4*)(x + (size_t)t * IN_F);
        float4 v[8];
        float m = 0.0f;
#pragma unroll
        for (int i = 0; i < 8; i++) {
            v[i] = xr[lane + 32 * i];
            m = fmaxf(m, fmaxf(fmaxf(fabsf(v[i].x), fabsf(v[i].y)),
                               fmaxf(fabsf(v[i].z), fabsf(v[i].w))));
        }
#pragma unroll
        for (int o = 16; o > 0; o >>= 1) m = fmaxf(m, __shfl_xor_sync(0xFFFFFFFFu, m, o));
        float scale = __fdiv_rn(fmaxf(m, 1e-8f), 127.0f);

#pragma unroll
        for (int i = 0; i < 8; i++) {
            float q0 = fminf(fmaxf(rintf(__fdiv_rn(v[i].x, scale)), -128.0f), 127.0f);
            float q1 = fminf(fmaxf(rintf(__fdiv_rn(v[i].y, scale)), -128.0f), 127.0f);
            float q2 = fminf(fmaxf(rintf(__fdiv_rn(v[i].z, scale)), -128.0f), 127.0f);
            float q3 = fminf(fmaxf(rintf(__fdiv_rn(v[i].w, scale)), -128.0f), 127.0f);
            uint2 pr = make_uint2(bf16x2(q0, q1), bf16x2(q2, q3));
            *(uint2*)(sm + warp * SM_STRIDE + 8 * lane + 256 * i) = pr;
        }
        if (lane == 0) g_xs[t] = scale;
        __syncthreads();

#pragma unroll
        for (int it = 0; it < 4; it++) {
            int u = tid + it * 512;
            int kb = u >> 5, l2 = u & 31;
            int g = l2 >> 2, t4 = l2 & 3;
            int bo = kb * 32 + t4 * 4;
            uint4 f;
            f.x = *(const uint32_t*)(sm + g * SM_STRIDE + bo);
            f.y = *(const uint32_t*)(sm + (g + 8) * SM_STRIDE + bo);
            f.z = *(const uint32_t*)(sm + g * SM_STRIDE + bo + 16);
            f.w = *(const uint32_t*)(sm + (g + 8) * SM_STRIDE + bo + 16);
            *(uint4*)((int8_t*)g_xa + ((((size_t)mg * 64 + kb) << 5) + l2) * 16) = f;
        }
    } else {
        // ---- weight binarize -> packed sign bits ----
        int wb = blockIdx.x - qBlocks;
        int o = wb * 16 + warp;
        const float4* wr = (const float4*)(w + (size_t)o * IN_F);
        float am[8];
#pragma unroll
        for (int i = 0; i < 8; i++) {
            float4 v = wr[lane + 32 * i];
            uint2 pr;
            pr.x = (((v.x > 0.0f) ? 0x3F80u : 0xBF80u))
                 | (((v.y > 0.0f) ? 0x3F80u : 0xBF80u) << 16);
            pr.y = (((v.z > 0.0f) ? 0x3F80u : 0xBF80u))
                 | (((v.w > 0.0f) ? 0x3F80u : 0xBF80u) << 16);
            *(uint2*)(sm + warp * SM_STRIDE + 8 * lane + 256 * i) = pr;
            am[i] = fmaxf(fmaxf(fabsf(v.x), fabsf(v.y)), fmaxf(fabsf(v.z), fabsf(v.w)));
        }
#pragma unroll
        for (int i = 0; i < 8; i++)
#pragma unroll
            for (int off = 16; off > 0; off >>= 1)
                am[i] = fmaxf(am[i], __shfl_xor_sync(0xFFFFFFFFu, am[i], off));
        if (lane == 0) {
            float s = 0.0f;
#pragma unroll
            for (int i = 0; i < 8; i++)
                s += __half2float(__float2half_rn(fmaxf(am[i], 1e-8f)));
            g_ws[o] = s * 0.125f;
        }
        __syncthreads();

        // writeout: 2048 bytes (2 ng x 32 kbp x 32 lanes), 4 per thread
#pragma unroll
        for (int it = 0; it < 4; it++) {
            int u = tid + it * 512;
            int nh = u >> 10, kbp = (u >> 5) & 31, l2 = u & 31;
            int row = nh * 8 + (l2 >> 2);
            int bo = kbp * 64 + (l2 & 3) * 4;
            uint32_t fx = *(const uint32_t*)(sm + row * SM_STRIDE + bo);
            uint32_t fy = *(const uint32_t*)(sm + row * SM_STRIDE + bo + 16);
            uint32_t fz = *(const uint32_t*)(sm + row * SM_STRIDE + bo + 32);
            uint32_t fw = *(const uint32_t*)(sm + row * SM_STRIDE + bo + 48);
            // bit = 1 for +1 (stored 0x3F80 -> sign bit 0)
            uint32_t b = ((~fx >> 15) & 1u)  | ((~fx >> 30) & 2u)
                       | ((~fy >> 13) & 4u)  | ((~fy >> 28) & 8u)
                       | ((~fz >> 11) & 16u) | ((~fz >> 26) & 32u)
                       | ((~fw >> 9) & 64u)  | ((~fw >> 24) & 128u);
            int ngg = wb * 2 + nh;            // global n-group 0..127
            int n_blk = ngg >> 4;
            int ngt = ngg & 15;
            int wn = ngt >> 2, jj = ngt & 3;
            int chunk = kbp >> 1, kk = kbp & 1;
            size_t off = ((((size_t)(n_blk * 16 + chunk) * 4 + wn) * 32 + l2) * 4 + jj) * 2 + kk;
            g_wbits[off] = (uint8_t)b;
        }
    }
}

// ---------------- GEMM: 128x128 tile, 2 CTAs/SM, bit-packed B, 4-stage ----------------
__global__ void __launch_bounds__(256, 2)
onebit_gemm_kernel(const float* __restrict__ bias, float* __restrict__ out) {
    extern __shared__ char smem[];
    uint32_t SB = smem_u32(smem);

    int tid = threadIdx.x, warp = tid >> 5, lane = tid & 31;
    int wm = warp >> 2;            // 0..1
    int wn = warp & 3;             // 0..3
    int n_blk = blockIdx.x & 7;
    int m_blk = blockIdx.x >> 3;
    int m0 = m_blk * TILE_M, n0 = n_blk * TILE_N;

    int mgB0 = m_blk * 8;

    const uint4* Ag = (const uint4*)g_xa;

    auto stage_chunk = [&](int c) {
        uint32_t dst = SB + (uint32_t)(c % NSTAGE) * STAGE_BYTES;
        // A: 1024 uint4 over 256 threads
#pragma unroll
        for (int it = 0; it < 4; it++) {
            int u = tid + it * 256;
            int mg = u >> 7, kbl = (u >> 5) & 3, l2 = u & 31;
            cp16(dst + (uint32_t)u * 16,
                 Ag + ((((size_t)(mgB0 + mg)) * 64 + c * KB_CH + kbl) << 5) + l2);
        }
        // B bits: 1KB = 64 cp16 by first 64 threads
        if (tid < 64) {
            cp16(dst + A_CH_BYTES + (uint32_t)tid * 16,
                 g_wbits + (((size_t)(n_blk * 16 + c)) << 10) + tid * 16);
        }
        asm volatile("cp.async.commit_group;" ::: "memory");
    };

    stage_chunk(0);
    stage_chunk(1);
    stage_chunk(2);

    float acc[4][4][4];
#pragma unroll
    for (int i = 0; i < 4; i++)
#pragma unroll
        for (int j = 0; j < 4; j++)
#pragma unroll
            for (int q = 0; q < 4; q++) acc[i][j][q] = 0.0f;

    uint32_t aWOff = (uint32_t)(((wm * 4) * KB_CH) * 32 + lane) * 16;
    uint32_t bWOff = (uint32_t)A_CH_BYTES + (uint32_t)(wn * 256 + lane * 8);

#pragma unroll 1
    for (int c = 0; c < NCHUNK; c++) {
        // newest committed group here = chunk c+2 -> wait 2 retires chunk c
        asm volatile("cp.async.wait_group 2;" ::: "memory");
        __syncthreads();

        uint32_t buf = SB + (uint32_t)(c % NSTAGE) * STAGE_BYTES;
        uint32_t aW = buf + aWOff;

        uint2 bb;                 // this warp's 8 B-bit bytes: [jj 4][kbpl 2]
        lds64(bb, buf + bWOff);

#pragma unroll
        for (int kbpl = 0; kbpl < KB_CH / 2; kbpl++) {
            // expand B fragments: bytes jj*2+kbpl
            uint32_t e[4][4];
#pragma unroll
            for (int j = 0; j < 4; j++) {
                uint32_t word = (j < 2) ? bb.x : bb.y;
                uint32_t byte = (word >> ((((j & 1) << 1) | kbpl) << 3)) & 0xFFu;
#pragma unroll
                for (int q = 0; q < 4; q++) e[j][q] = bexp(byte, q);
            }

            uint4 af[4];
#pragma unroll
            for (int i = 0; i < 4; i++)
                lds128(af[i], aW + (uint32_t)((i * KB_CH + 2 * kbpl) * 32) * 16);
#pragma unroll
            for (int i = 0; i < 4; i++)
#pragma unroll
                for (int j = 0; j < 4; j++)
                    mma_bf16(acc[i][j], af[i].x, af[i].y, af[i].z, af[i].w,
                             e[j][0], e[j][1]);

#pragma unroll
            for (int i = 0; i < 4; i++)
                lds128(af[i], aW + (uint32_t)((i * KB_CH + 2 * kbpl + 1) * 32) * 16);
#pragma unroll
            for (int i = 0; i < 4; i++)
#pragma unroll
                for (int j = 0; j < 4; j++)
                    mma_bf16(acc[i][j], af[i].x, af[i].y, af[i].z, af[i].w,
                             e[j][2], e[j][3]);
        }

        if (c + 3 < NCHUNK) {
            stage_chunk(c + 3);
        } else {
            // uniform group accounting past the last real stage (race fix)
            asm volatile("cp.async.commit_group;" ::: "memory");
        }
    }

    // ---------------- fused epilogue ----------------
    int g = lane >> 2, t4 = lane & 3;
#pragma unroll
    for (int i = 0; i < 4; i++) {
        int r0 = m0 + wm * 64 + i * 16 + g;
        float sx0 = g_xs[r0];
        float sx1 = g_xs[r0 + 8];
        float* o0 = out + (size_t)r0 * OUT_F + n0;
        float* o1 = o0 + (size_t)8 * OUT_F;
#pragma unroll
        for (int j = 0; j < 4; j++) {
            int cc = wn * 32 + j * 8 + t4 * 2;
            float w0 = g_ws[n0 + cc], w1 = g_ws[n0 + cc + 1];
            float b0 = bias[n0 + cc], b1 = bias[n0 + cc + 1];
            float2 v0, v1;
            v0.x = acc[i][j][0] * sx0 * w0 + b0;
            v0.y = acc[i][j][1] * sx0 * w1 + b1;
            v1.x = acc[i][j][2] * sx1 * w0 + b0;
            v1.y = acc[i][j][3] * sx1 * w1 + b1;
            *(float2*)(o0 + cc) = v0;
            *(float2*)(o1 + cc) = v1;
        }
    }
}

// ---------------- launch ----------------
extern "C" void kernel_launch(void* const* d_in, const int* in_sizes, int n_in,
                              void* d_out, int out_size) {
    const float* x    = (const float*)d_in[0];
    const float* w    = (const float*)d_in[1];
    const float* bias = (const float*)d_in[2];
    float* out = (float*)d_out;
    int tokens = in_sizes[0] / IN_F;

    int qBlocks = tokens / 16;
    prep_kernel<<<qBlocks + OUT_F / 16, 512>>>(x, w, qBlocks);

    cudaFuncSetAttribute(onebit_gemm_kernel,
                         cudaFuncAttributeMaxDynamicSharedMemorySize, GEMM_SMEM);
    int mtiles = tokens / TILE_M;
    onebit_gemm_kernel<<<mtiles * (OUT_F / TILE_N), 256, GEMM_SMEM>>>(bias, out);
}

// round 17
// speedup vs baseline: 1.0496x; 1.0496x over previous
#include <cuda_runtime.h>
#include <cuda_fp16.h>
#include <cuda_bf16.h>
#include <cstdint>
#include <cstddef>

// ---------------- problem constants ----------------
#define IN_F   1024
#define OUT_F  1024
#define MAX_TOKENS 32768
#define TILE_M 128
#define TILE_N 128

#define SM_STRIDE 2064    // prep-kernel smem row pad

// GEMM pipeline: chunk = 4 kb (2 kbp), 3-stage, 2 CTAs/SM
#define KB_CH    4
#define NCHUNK   16                                  // 64 kb total
#define NSTAGE   3
#define A_CH_BYTES (8 * KB_CH * 32 * 16)             // 16384
#define B_CH_BYTES (16 * (KB_CH/2) * 32 * 16)        // 16384
#define STAGE_BYTES (A_CH_BYTES + B_CH_BYTES)        // 32768
#define GEMM_SMEM (NSTAGE * STAGE_BYTES)             // 98304 per CTA (x2 = 192KB/SM)

// ---------------- scratch: bf16 fragment-major operand layouts ----------------
__device__ __align__(16) __nv_bfloat16 g_xa[(size_t)MAX_TOKENS * IN_F];
__device__ float g_xs[MAX_TOKENS];
__device__ __align__(16) __nv_bfloat16 g_wb[(size_t)OUT_F * IN_F];
__device__ float g_ws[OUT_F];

// ---------------- helpers ----------------
static __device__ __forceinline__ void mma_bf16(float* c, uint32_t a0, uint32_t a1,
                                                uint32_t a2, uint32_t a3,
                                                uint32_t b0, uint32_t b1) {
    asm volatile(
        "mma.sync.aligned.m16n8k16.row.col.f32.bf16.bf16.f32 "
        "{%0,%1,%2,%3}, {%4,%5,%6,%7}, {%8,%9}, {%0,%1,%2,%3};"
        : "+f"(c[0]), "+f"(c[1]), "+f"(c[2]), "+f"(c[3])
        : "r"(a0), "r"(a1), "r"(a2), "r"(a3), "r"(b0), "r"(b1));
}
static __device__ __forceinline__ uint32_t bf16x2(float lo, float hi) {
    return (uint32_t)__bfloat16_as_ushort(__float2bfloat16_rn(lo))
         | ((uint32_t)__bfloat16_as_ushort(__float2bfloat16_rn(hi)) << 16);
}
static __device__ __forceinline__ uint32_t smem_u32(const void* p) {
    uint32_t a;
    asm("{ .reg .u64 t; cvta.to.shared.u64 t, %1; cvt.u32.u64 %0, t; }" : "=r"(a) : "l"(p));
    return a;
}
static __device__ __forceinline__ void cp16(uint32_t s, const void* g) {
    asm volatile("cp.async.cg.shared.global [%0], [%1], 16;" :: "r"(s), "l"(g));
}
static __device__ __forceinline__ void lds128(uint4& v, uint32_t addr) {
    asm volatile("ld.shared.v4.u32 {%0,%1,%2,%3}, [%4];"
                 : "=r"(v.x), "=r"(v.y), "=r"(v.z), "=r"(v.w) : "r"(addr));
}

// ---------------- fused prep kernel ----------------
__global__ void __launch_bounds__(512) prep_kernel(const float* __restrict__ x,
                                                   const float* __restrict__ w,
                                                   int qBlocks) {
    __shared__ int8_t sm[16 * SM_STRIDE];
    int tid = threadIdx.x, warp = tid >> 5, lane = tid & 31;

    if ((int)blockIdx.x < qBlocks) {
        // ---- activation quantization: 16 tokens per block ----
        int mg = blockIdx.x;
        int t = mg * 16 + warp;
        const float4* xr = (const float4*)(x + (size_t)t * IN_F);
        float4 v[8];
        float m = 0.0f;
#pragma unroll
        for (int i = 0; i < 8; i++) {
            v[i] = xr[lane + 32 * i];
            m = fmaxf(m, fmaxf(fmaxf(fabsf(v[i].x), fabsf(v[i].y)),
                               fmaxf(fabsf(v[i].z), fabsf(v[i].w))));
        }
#pragma unroll
        for (int o = 16; o > 0; o >>= 1) m = fmaxf(m, __shfl_xor_sync(0xFFFFFFFFu, m, o));
        float scale = __fdiv_rn(fmaxf(m, 1e-8f), 127.0f);
        // one correctly-rounded reciprocal per token; per-element FMUL replaces
        // 32 full-precision divisions (quant-bin flips are ~2ulp-rare and
        // norm-invisible at the 1e-3 threshold)
        float inv = __fdiv_rn(1.0f, scale);

#pragma unroll
        for (int i = 0; i < 8; i++) {
            float q0 = fminf(fmaxf(rintf(v[i].x * inv), -128.0f), 127.0f);
            float q1 = fminf(fmaxf(rintf(v[i].y * inv), -128.0f), 127.0f);
            float q2 = fminf(fmaxf(rintf(v[i].z * inv), -128.0f), 127.0f);
            float q3 = fminf(fmaxf(rintf(v[i].w * inv), -128.0f), 127.0f);
            uint2 pr = make_uint2(bf16x2(q0, q1), bf16x2(q2, q3));
            *(uint2*)(sm + warp * SM_STRIDE + 8 * lane + 256 * i) = pr;
        }
        if (lane == 0) g_xs[t] = scale;
        __syncthreads();

#pragma unroll
        for (int it = 0; it < 4; it++) {
            int u = tid + it * 512;
            int kb = u >> 5, l2 = u & 31;
            int g = l2 >> 2, t4 = l2 & 3;
            int bo = kb * 32 + t4 * 4;
            uint4 f;
            f.x = *(const uint32_t*)(sm + g * SM_STRIDE + bo);
            f.y = *(const uint32_t*)(sm + (g + 8) * SM_STRIDE + bo);
            f.z = *(const uint32_t*)(sm + g * SM_STRIDE + bo + 16);
            f.w = *(const uint32_t*)(sm + (g + 8) * SM_STRIDE + bo + 16);
            *(uint4*)((int8_t*)g_xa + ((((size_t)mg * 64 + kb) << 5) + l2) * 16) = f;
        }
    } else {
        // ---- weight binarize: 16 rows per block ----
        int wb = blockIdx.x - qBlocks;
        int o = wb * 16 + warp;
        const float4* wr = (const float4*)(w + (size_t)o * IN_F);
        float am[8];
#pragma unroll
        for (int i = 0; i < 8; i++) {
            float4 v = wr[lane + 32 * i];
            uint2 pr;
            pr.x = (((v.x > 0.0f) ? 0x3F80u : 0xBF80u))
                 | (((v.y > 0.0f) ? 0x3F80u : 0xBF80u) << 16);
            pr.y = (((v.z > 0.0f) ? 0x3F80u : 0xBF80u))
                 | (((v.w > 0.0f) ? 0x3F80u : 0xBF80u) << 16);
            *(uint2*)(sm + warp * SM_STRIDE + 8 * lane + 256 * i) = pr;
            am[i] = fmaxf(fmaxf(fabsf(v.x), fabsf(v.y)), fmaxf(fabsf(v.z), fabsf(v.w)));
        }
#pragma unroll
        for (int i = 0; i < 8; i++)
#pragma unroll
            for (int off = 16; off > 0; off >>= 1)
                am[i] = fmaxf(am[i], __shfl_xor_sync(0xFFFFFFFFu, am[i], off));
        if (lane == 0) {
            float s = 0.0f;
#pragma unroll
            for (int i = 0; i < 8; i++)
                s += __half2float(__float2half_rn(fmaxf(am[i], 1e-8f)));
            g_ws[o] = s * 0.125f;
        }
        __syncthreads();

#pragma unroll
        for (int it = 0; it < 4; it++) {
            int u = tid + it * 512;
            int nh = u >> 10, kbp = (u >> 5) & 31, l2 = u & 31;
            int c = l2 >> 2, t4 = l2 & 3;
            int row = nh * 8 + c;
            int bo = kbp * 64 + t4 * 4;
            uint4 f;
            f.x = *(const uint32_t*)(sm + row * SM_STRIDE + bo);
            f.y = *(const uint32_t*)(sm + row * SM_STRIDE + bo + 16);
            f.z = *(const uint32_t*)(sm + row * SM_STRIDE + bo + 32);
            f.w = *(const uint32_t*)(sm + row * SM_STRIDE + bo + 48);
            int ng = wb * 2 + nh;
            *(uint4*)((int8_t*)g_wb + ((((size_t)ng * 32 + kbp) << 5) + l2) * 16) = f;
        }
    }
}

// ---------------- GEMM: 128x128 tile, 256 threads, 2 CTAs/SM, early staging ----------------
__global__ void __launch_bounds__(256, 2)
onebit_gemm_kernel(const float* __restrict__ bias, float* __restrict__ out) {
    extern __shared__ char smem[];
    uint32_t SB = smem_u32(smem);

    int tid = threadIdx.x, warp = tid >> 5, lane = tid & 31;
    int wm = warp >> 2;            // 0..1 -> 64-row slab of 128
    int wn = warp & 3;             // 0..3 -> 32-col slab of 128
    int n_blk = blockIdx.x & 7;
    int m_blk = blockIdx.x >> 3;
    int m0 = m_blk * TILE_M, n0 = n_blk * TILE_N;

    int mgB0 = m_blk * 8;          // 8 m-groups per tile
    int ngB0 = n_blk * 16;         // 16 n-groups per tile

    const uint4* Ag = (const uint4*)g_xa;       // [(mg*64 + kb)*32 + lane]
    const uint4* Bg = (const uint4*)g_wb;       // [(ng*32 + kbp)*32 + lane]

    // stage chunk c (4 kb of A, 2 kbp of B) into buffer (c % 3): 2048 cp16 / 256 thr
    auto stage_chunk = [&](int c) {
        uint32_t dst = SB + (uint32_t)(c % NSTAGE) * STAGE_BYTES;
        // A: 1024 uint4; smem order [mg 0..7][kbl 0..3][lane]
#pragma unroll
        for (int it = 0; it < 4; it++) {
            int u = tid + it * 256;
            int mg = u >> 7, kbl = (u >> 5) & 3, l2 = u & 31;
            cp16(dst + (uint32_t)u * 16,
                 Ag + ((((size_t)(mgB0 + mg)) * 64 + c * KB_CH + kbl) << 5) + l2);
        }
        // B: 1024 uint4; smem order [ng 0..15][kbpl 0..1][lane]
#pragma unroll
        for (int it = 0; it < 4; it++) {
            int u = tid + it * 256;
            int ng = u >> 6, kbpl = (u >> 5) & 1, l2 = u & 31;
            cp16(dst + A_CH_BYTES + (uint32_t)u * 16,
                 Bg + ((((size_t)(ngB0 + ng)) * 32 + c * (KB_CH / 2) + kbpl) << 5) + l2);
        }
        asm volatile("cp.async.commit_group;" ::: "memory");
    };

    stage_chunk(0);
    stage_chunk(1);

    float acc[4][4][4];
#pragma unroll
    for (int i = 0; i < 4; i++)
#pragma unroll
        for (int j = 0; j < 4; j++)
#pragma unroll
            for (int q = 0; q < 4; q++) acc[i][j][q] = 0.0f;

    uint32_t aWOff = (uint32_t)(((wm * 4) * KB_CH) * 32 + lane) * 16;
    uint32_t bWOff = (uint32_t)A_CH_BYTES
                   + (uint32_t)(((wn * 4) * (KB_CH / 2)) * 32 + lane) * 16;

#pragma unroll 1
    for (int c = 0; c < NCHUNK; c++) {
        // Invariant: newest committed group here is chunk c+1's (empty commits
        // keep the count uniform past the last real stage), so wait_group 1
        // guarantees chunk c's data has fully landed.
        asm volatile("cp.async.wait_group 1;" ::: "memory");
        __syncthreads();

        // Early staging: buffer (c+2)%3 == (c-1)%3 was fully consumed before
        // the barrier above, so issuing here is WAR-safe and gives the loads a
        // full chunk of extra lead while this chunk computes.
        if (c + 2 < NCHUNK) {
            stage_chunk(c + 2);
        } else {
            asm volatile("cp.async.commit_group;" ::: "memory");  // uniform accounting
        }

        uint32_t buf = SB + (uint32_t)(c % NSTAGE) * STAGE_BYTES;
        uint32_t aW = buf + aWOff;
        uint32_t bW = buf + bWOff;

#pragma unroll
        for (int kbpl = 0; kbpl < KB_CH / 2; kbpl++) {
            uint4 bf[4];
#pragma unroll
            for (int j = 0; j < 4; j++)
                lds128(bf[j], bW + (uint32_t)((j * (KB_CH / 2) + kbpl) * 32) * 16);

            uint4 af[4];
#pragma unroll
            for (int i = 0; i < 4; i++)
                lds128(af[i], aW + (uint32_t)((i * KB_CH + 2 * kbpl) * 32) * 16);
#pragma unroll
            for (int i = 0; i < 4; i++)
#pragma unroll
                for (int j = 0; j < 4; j++)
                    mma_bf16(acc[i][j], af[i].x, af[i].y, af[i].z, af[i].w,
                             bf[j].x, bf[j].y);

#pragma unroll
            for (int i = 0; i < 4; i++)
                lds128(af[i], aW + (uint32_t)((i * KB_CH + 2 * kbpl + 1) * 32) * 16);
#pragma unroll
            for (int i = 0; i < 4; i++)
#pragma unroll
                for (int j = 0; j < 4; j++)
                    mma_bf16(acc[i][j], af[i].x, af[i].y, af[i].z, af[i].w,
                             bf[j].z, bf[j].w);
        }
    }

    // ---------------- fused epilogue ----------------
    int g = lane >> 2, t4 = lane & 3;
#pragma unroll
    for (int i = 0; i < 4; i++) {
        int r0 = m0 + wm * 64 + i * 16 + g;
        float sx0 = g_xs[r0];
        float sx1 = g_xs[r0 + 8];
        float* o0 = out + (size_t)r0 * OUT_F + n0;
        float* o1 = o0 + (size_t)8 * OUT_F;
#pragma unroll
        for (int j = 0; j < 4; j++) {
            int cc = wn * 32 + j * 8 + t4 * 2;
            float w0 = g_ws[n0 + cc], w1 = g_ws[n0 + cc + 1];
            float b0 = bias[n0 + cc], b1 = bias[n0 + cc + 1];
            float2 v0, v1;
            v0.x = acc[i][j][0] * sx0 * w0 + b0;
            v0.y = acc[i][j][1] * sx0 * w1 + b1;
            v1.x = acc[i][j][2] * sx1 * w0 + b0;
            v1.y = acc[i][j][3] * sx1 * w1 + b1;
            *(float2*)(o0 + cc) = v0;
            *(float2*)(o1 + cc) = v1;
        }
    }
}

// ---------------- launch ----------------
extern "C" void kernel_launch(void* const* d_in, const int* in_sizes, int n_in,
                              void* d_out, int out_size) {
    const float* x    = (const float*)d_in[0];
    const float* w    = (const float*)d_in[1];
    const float* bias = (const float*)d_in[2];
    float* out = (float*)d_out;
    int tokens = in_sizes[0] / IN_F;

    int qBlocks = tokens / 16;
    prep_kernel<<<qBlocks + OUT_F / 16, 512>>>(x, w, qBlocks);

    cudaFuncSetAttribute(onebit_gemm_kernel,
                         cudaFuncAttributeMaxDynamicSharedMemorySize, GEMM_SMEM);
    int mtiles = tokens / TILE_M;
    onebit_gemm_kernel<<<mtiles * (OUT_F / TILE_N), 256, GEMM_SMEM>>>(bias, out);
}